// round 12
// baseline (speedup 1.0000x reference)
#include <cuda_runtime.h>
#include <math.h>
#include <stdint.h>

// Problem dims
#define B_  256
#define T_  128
#define I_  256
#define H_  512
#define G4  2048   // 4*H
#define K0  768    // I + H
#define K1  1024   // H + H

// GEMM tile: block 64(m) x 128(n), 8 warps (2m x 4n), warp 32x32, stage BK=32
#define BM  64
#define BN  128
#define BKK 32
#define DEPTH 4

#define A_ST (2 * BM * 16)            // 2048 words
#define B_ST (2 * BN * 16)            // 4096 words
#define STAGE_WORDS (A_ST + B_ST)     // 6144 words = 24KB
#define STAGE_BYTES (STAGE_WORDS * 4)
#define SMEM_BYTES (DEPTH * STAGE_BYTES)   // 98304

// k16 interleave: position pos holds k = (pos>>2) + 4*(pos&3); pos(k) = 4*(k&3) + ((k>>2)&3)
__host__ __device__ __forceinline__ int kperm(int j) {
    return (j & ~15) | (4 * (j & 3) + ((j >> 2) & 3));
}

// ---------------- scratch ----------------
__device__ float g_W0p[(K0/16) * G4 * 16];  // [k/16][p][16 pos], tf32, k-interleaved
__device__ float g_W1p[(K1/16) * G4 * 16];
__device__ float g_b0p[G4];
__device__ float g_b1p[G4];
__device__ float g_x32[B_ * T_ * I_];       // tf32-rounded, k-interleaved per 16
__device__ float g_h0 [2][B_ * H_];         // rounded, UNMASKED, j-interleaved
__device__ float g_h0m[2][B_ * H_];         // rounded, masked, j-interleaved
__device__ float g_h1m[2][B_ * H_];
__device__ float g_c0[B_ * H_];             // natural
__device__ float g_c1[B_ * H_];
__device__ float g_h0f[B_ * H_];            // exact h(T-1), natural
__device__ float g_h1f[B_ * H_];

// gate-column permutation: p -> original gate row q*H + j (groups of 16 cols = 4 units)
__device__ __forceinline__ int p2norig(int p) {
    int g = p >> 4, pp = p & 15;
    int q = (pp < 8) ? (pp & 1) : (2 + (pp & 1));
    int u = (pp < 8) ? (pp >> 1) : ((pp - 8) >> 1);
    return q * H_ + g * 4 + u;
}

__device__ __forceinline__ uint32_t tf32_bits(float x) {
    uint32_t u;
    asm("cvt.rna.tf32.f32 %0, %1;" : "=r"(u) : "f"(x));
    return u;
}

__device__ __forceinline__ void cp16(uint32_t dst, const void* src) {
    asm volatile("cp.async.cg.shared.global [%0], [%1], 16;" :: "r"(dst), "l"(src));
}

// ---------------- prologue ----------------
__global__ void permute_kernel(const float* __restrict__ input,
                               const float* __restrict__ Wih0, const float* __restrict__ Whh0,
                               const float* __restrict__ bih0, const float* __restrict__ bhh0,
                               const float* __restrict__ Wih1, const float* __restrict__ Whh1,
                               const float* __restrict__ bih1, const float* __restrict__ bhh1)
{
    int stride = gridDim.x * blockDim.x;
    int tid0 = blockIdx.x * blockDim.x + threadIdx.x;

    for (int idx = tid0; idx < B_ * T_ * I_; idx += stride) {
        int base = idx & ~15, pos = idx & 15;
        int ksrc = base + (pos >> 2) + 4 * (pos & 3);
        g_x32[idx] = __uint_as_float(tf32_bits(input[ksrc]));
    }
    for (int idx = tid0; idx < (K0/16) * G4 * 16; idx += stride) {
        int pos = idx & 15;
        int p  = (idx >> 4) & (G4 - 1);
        int kb = idx >> 15;
        int k = kb * 16 + (pos >> 2) + 4 * (pos & 3);
        int norig = p2norig(p);
        float v = (k < I_) ? Wih0[norig * I_ + k] : Whh0[norig * H_ + (k - I_)];
        g_W0p[idx] = __uint_as_float(tf32_bits(v));
    }
    for (int idx = tid0; idx < (K1/16) * G4 * 16; idx += stride) {
        int pos = idx & 15;
        int p  = (idx >> 4) & (G4 - 1);
        int kb = idx >> 15;
        int k = kb * 16 + (pos >> 2) + 4 * (pos & 3);
        int norig = p2norig(p);
        float v = (k < H_) ? Wih1[norig * H_ + k] : Whh1[norig * H_ + (k - H_)];
        g_W1p[idx] = __uint_as_float(tf32_bits(v));
    }
    for (int p = tid0; p < G4; p += stride) {
        int norig = p2norig(p);
        g_b0p[p] = bih0[norig] + bhh0[norig];
        g_b1p[p] = bih1[norig] + bhh1[norig];
    }
}

__global__ void init_state_kernel(const float* __restrict__ h, const float* __restrict__ c,
                                  const int* __restrict__ is_init)
{
    int stride = gridDim.x * blockDim.x;
    for (int idx = blockIdx.x * blockDim.x + threadIdx.x; idx < B_ * H_; idx += stride) {
        int b = idx / H_, j = idx - b * H_;
        float m0 = is_init[b * T_] ? 0.0f : 1.0f;
        int jp = kperm(j);
        g_h0m[0][b * H_ + jp] = __uint_as_float(tf32_bits(h[b * 2 * H_ + j])) * m0;
        g_h1m[0][b * H_ + jp] = __uint_as_float(tf32_bits(h[b * 2 * H_ + H_ + j])) * m0;
        g_c0[idx] = c[b * 2 * H_ + j];
        g_c1[idx] = c[b * 2 * H_ + H_ + j];
    }
}

// ---------------- fused tf32 mma GEMM + LSTM cell ----------------
template<int LAYER>
__device__ __forceinline__ void lstm_step_body(
    uint32_t* __restrict__ smem,
    const int* __restrict__ is_init,
    float* __restrict__ out,
    int t)
{
    constexpr int K = (LAYER == 0) ? K0 : K1;
    constexpr int NSTAGE = K / BKK;                 // 24 or 32 (both % 4 == 0)
    const float* Wp = (LAYER == 0) ? g_W0p : g_W1p;
    const float* bp = (LAYER == 0) ? g_b0p : g_b1p;
    const int ping = t & 1;
    const float* hmsk = (LAYER == 0) ? g_h0m[ping] : g_h1m[ping];
    const float* h0u  = g_h0[ping ^ 1];
    float* cbuf = (LAYER == 0) ? g_c0 : g_c1;

    const int tid = threadIdx.x;
    const int bn = blockIdx.x;               // 0..15 (128 gate cols)
    const int bm = blockIdx.y;               // 0..3  (64 batch rows)
    const int wid = tid >> 5, lane = tid & 31;
    const int wm = wid >> 2;                 // 0..1
    const int wn = wid & 3;                  // 0..3
    const int gi = lane >> 2;                // 0..7
    const int tg = lane & 3;                 // 0..3

    const uint32_t sbase = (uint32_t)__cvta_generic_to_shared(smem);

    // ---- hoisted producer state ----
    // A: 2 chunks/thread; two region pointers + threshold; add k0 at issue time
    const float* pA0[2]; const float* pA1[2]; int thrA[2]; uint32_t dstA[2];
    #pragma unroll
    for (int hh = 0; hh < 2; hh++) {
        int c = tid + 256 * hh;
        int qc = c & 3, row = (c >> 2) & 63, ks16 = c >> 8;
        int gb = bm * BM + row;
        if (LAYER == 0) {
            pA0[hh] = g_x32 + (size_t)gb * T_ * I_ + (size_t)t * I_ + ks16 * 16 + qc * 4;
            pA1[hh] = hmsk + (size_t)gb * H_ + ks16 * 16 + qc * 4 - I_;
            thrA[hh] = I_ - ks16 * 16;
        } else {
            pA0[hh] = h0u + (size_t)gb * H_ + ks16 * 16 + qc * 4;
            pA1[hh] = hmsk + (size_t)gb * H_ + ks16 * 16 + qc * 4 - H_;
            thrA[hh] = H_ - ks16 * 16;
        }
        dstA[hh] = sbase + (ks16 * BM * 16 + row * 16 + qc * 4) * 4;
    }
    // B: 4 chunks/thread; pointer advances by 2*G4*16 floats per stage
    const float* pB[4]; uint32_t dstB[4];
    #pragma unroll
    for (int hh = 0; hh < 4; hh++) {
        int c = tid + 256 * hh;
        int qc = c & 3, n = (c >> 2) & 127, ks16 = c >> 9;
        pB[hh] = Wp + ((size_t)ks16 * G4 + bn * BN + n) * 16 + qc * 4;
        dstB[hh] = sbase + (A_ST + ks16 * BN * 16 + n * 16 + qc * 4) * 4;
    }

    auto issue = [&](int k0, uint32_t bo) {
        #pragma unroll
        for (int hh = 0; hh < 2; hh++) {
            const float* s = (k0 < thrA[hh]) ? (pA0[hh] + k0) : (pA1[hh] + k0);
            cp16(dstA[hh] + bo, s);
        }
        #pragma unroll
        for (int hh = 0; hh < 4; hh++) {
            cp16(dstB[hh] + bo, pB[hh]);
            pB[hh] += 2 * G4 * 16;
        }
    };

    float acc[2][4][4] = {};

    issue(0, 0);
    asm volatile("cp.async.commit_group;" ::: "memory");
    issue(BKK, STAGE_BYTES);
    asm volatile("cp.async.commit_group;" ::: "memory");
    issue(2 * BKK, 2 * STAGE_BYTES);
    asm volatile("cp.async.commit_group;" ::: "memory");

    int kIss = 3 * BKK;
    for (int st4 = 0; st4 < NSTAGE; st4 += 4) {
        #pragma unroll
        for (int ii = 0; ii < 4; ii++) {
            const int st = st4 + ii;
            asm volatile("cp.async.wait_group 2;" ::: "memory");
            __syncthreads();

            if (st + 3 < NSTAGE)
                issue(kIss, (uint32_t)(((ii + 3) & 3) * STAGE_BYTES));
            kIss += BKK;
            asm volatile("cp.async.commit_group;" ::: "memory");

            const uint32_t* Ab = smem + ii * STAGE_WORDS;   // compile-time offset
            const uint32_t* Bb = Ab + A_ST;

            #pragma unroll
            for (int ks16 = 0; ks16 < 2; ks16++) {
                uint4 va[2][2], vb[4];
                #pragma unroll
                for (int mt = 0; mt < 2; mt++) {
                    int m0 = wm * 32 + mt * 16 + gi;
                    va[mt][0] = *(const uint4*)(Ab + ks16 * BM * 16 + m0 * 16 + tg * 4);
                    va[mt][1] = *(const uint4*)(Ab + ks16 * BM * 16 + (m0 + 8) * 16 + tg * 4);
                }
                #pragma unroll
                for (int nt = 0; nt < 4; nt++) {
                    int n0 = wn * 32 + nt * 8 + gi;
                    vb[nt] = *(const uint4*)(Bb + ks16 * BN * 16 + n0 * 16 + tg * 4);
                }
                #pragma unroll
                for (int mt = 0; mt < 2; mt++)
                    #pragma unroll
                    for (int nt = 0; nt < 4; nt++)
                        asm volatile(
                            "mma.sync.aligned.m16n8k8.row.col.f32.tf32.tf32.f32 "
                            "{%0,%1,%2,%3},{%4,%5,%6,%7},{%8,%9},{%0,%1,%2,%3};"
                            : "+f"(acc[mt][nt][0]), "+f"(acc[mt][nt][1]),
                              "+f"(acc[mt][nt][2]), "+f"(acc[mt][nt][3])
                            : "r"(va[mt][0].x), "r"(va[mt][1].x),
                              "r"(va[mt][0].y), "r"(va[mt][1].y),
                              "r"(vb[nt].x), "r"(vb[nt].y));
                #pragma unroll
                for (int mt = 0; mt < 2; mt++)
                    #pragma unroll
                    for (int nt = 0; nt < 4; nt++)
                        asm volatile(
                            "mma.sync.aligned.m16n8k8.row.col.f32.tf32.tf32.f32 "
                            "{%0,%1,%2,%3},{%4,%5,%6,%7},{%8,%9},{%0,%1,%2,%3};"
                            : "+f"(acc[mt][nt][0]), "+f"(acc[mt][nt][1]),
                              "+f"(acc[mt][nt][2]), "+f"(acc[mt][nt][3])
                            : "r"(va[mt][0].z), "r"(va[mt][1].z),
                              "r"(va[mt][0].w), "r"(va[mt][1].w),
                              "r"(vb[nt].z), "r"(vb[nt].w));
            }
        }
    }

    // ---- fused LSTM cell epilogue ----
    float* h0u_w = g_h0[ping ^ 1];
    float* hm_w  = (LAYER == 0) ? g_h0m[ping ^ 1] : g_h1m[ping ^ 1];
    float* hf_w  = (LAYER == 0) ? g_h0f : g_h1f;

    #pragma unroll
    for (int gp = 0; gp < 2; gp++) {
        const int g = bn * 8 + wn * 2 + gp;
        const int j = g * 4 + tg;
        const int jp = kperm(j);
        const float bi = bp[g * 16 + 2 * tg];
        const float bf = bp[g * 16 + 2 * tg + 1];
        const float bg = bp[g * 16 + 8 + 2 * tg];
        const float bo = bp[g * 16 + 9 + 2 * tg];

        #pragma unroll
        for (int mt = 0; mt < 2; mt++)
            #pragma unroll
            for (int rr = 0; rr < 2; rr++) {
                int b = bm * BM + wm * 32 + mt * 16 + rr * 8 + gi;
                float ig = acc[mt][2 * gp + 0][rr * 2 + 0] + bi;
                float fg = acc[mt][2 * gp + 0][rr * 2 + 1] + bf;
                float gg = acc[mt][2 * gp + 1][rr * 2 + 0] + bg;
                float og = acc[mt][2 * gp + 1][rr * 2 + 1] + bo;
                float si = 1.0f / (1.0f + expf(-ig));
                float sf = 1.0f / (1.0f + expf(-fg));
                float so = 1.0f / (1.0f + expf(-og));
                float tgh = tanhf(gg);
                float cold = is_init[b * T_ + t] ? 0.0f : cbuf[b * H_ + j];
                float cn = sf * cold + si * tgh;
                float hn = so * tanhf(cn);
                cbuf[b * H_ + j] = cn;

                float hr = __uint_as_float(tf32_bits(hn));
                float mnext = 1.0f;
                if (t + 1 < T_) mnext = is_init[b * T_ + t + 1] ? 0.0f : 1.0f;
                hm_w[b * H_ + jp] = hr * mnext;
                if (LAYER == 0) h0u_w[b * H_ + jp] = hr;
                if (t == T_ - 1) hf_w[b * H_ + j] = hn;
                if (LAYER == 1)
                    out[(size_t)b * T_ * H_ + (size_t)t * H_ + j] = hn;
            }
    }
}

// Wavefront-fused launch s: z=0 -> layer0(time s), z=1 -> layer1(time s-1).
__global__ void __launch_bounds__(256, 1) fused_step_kernel(
    const int* __restrict__ is_init,
    float* __restrict__ out,
    int s)
{
    extern __shared__ uint32_t smem[];
    if (blockIdx.z == 0) {
        if (s < T_) lstm_step_body<0>(smem, is_init, out, s);
    } else {
        if (s >= 1) lstm_step_body<1>(smem, is_init, out, s - 1);
    }
}

// ---------------- finalize ----------------
__global__ void finalize_kernel(float* __restrict__ out)
{
    const size_t off1 = (size_t)B_ * T_ * H_;
    const size_t off2 = off1 + (size_t)B_ * 2 * H_;
    int stride = gridDim.x * blockDim.x;
    for (int idx = blockIdx.x * blockDim.x + threadIdx.x; idx < B_ * H_; idx += stride) {
        int b = idx / H_, j = idx - b * H_;
        out[off1 + (size_t)b * 2 * H_ + j]      = g_h0f[idx];
        out[off1 + (size_t)b * 2 * H_ + H_ + j] = g_h1f[idx];
        out[off2 + (size_t)b * 2 * H_ + j]      = g_c0[idx];
        out[off2 + (size_t)b * 2 * H_ + H_ + j] = g_c1[idx];
    }
}

extern "C" void kernel_launch(void* const* d_in, const int* in_sizes, int n_in,
                              void* d_out, int out_size)
{
    const float* input   = (const float*)d_in[0];
    const int*   is_init = (const int*)d_in[1];
    const float* h       = (const float*)d_in[2];
    const float* c       = (const float*)d_in[3];
    const float* Wih0    = (const float*)d_in[4];
    const float* Whh0    = (const float*)d_in[5];
    const float* bih0    = (const float*)d_in[6];
    const float* bhh0    = (const float*)d_in[7];
    const float* Wih1    = (const float*)d_in[8];
    const float* Whh1    = (const float*)d_in[9];
    const float* bih1    = (const float*)d_in[10];
    const float* bhh1    = (const float*)d_in[11];
    float* out = (float*)d_out;

    static bool attr_set = false;
    if (!attr_set) {
        cudaFuncSetAttribute(fused_step_kernel,
                             cudaFuncAttributeMaxDynamicSharedMemorySize, SMEM_BYTES);
        attr_set = true;
    }

    permute_kernel<<<296, 256>>>(input, Wih0, Whh0, bih0, bhh0, Wih1, Whh1, bih1, bhh1);
    init_state_kernel<<<148, 256>>>(h, c, is_init);

    dim3 grid(G4 / BN, B_ / BM, 2);   // (16, 4, 2) = 128 blocks, single wave
    for (int s = 0; s <= T_; s++)
        fused_step_kernel<<<grid, 256, SMEM_BYTES>>>(is_init, out, s);

    finalize_kernel<<<148, 256>>>(out);
}

// round 13
// speedup vs baseline: 1.0176x; 1.0176x over previous
#include <cuda_runtime.h>
#include <math.h>
#include <stdint.h>

// Problem dims
#define B_  256
#define T_  128
#define I_  256
#define H_  512
#define G4  2048   // 4*H
#define K0  768    // I + H
#define K1  1024   // H + H

// GEMM tile: block 64(m) x 64(n), 8 warps (2m x 4n), warp 32x16, stage BK=32
#define BM  64
#define BN  64
#define BKK 32
#define DEPTH 4

#define A_ST (2 * BM * 16)            // 2048 words
#define B_ST (2 * BN * 16)            // 2048 words
#define STAGE_WORDS (A_ST + B_ST)     // 4096 words = 16KB
#define STAGE_BYTES (STAGE_WORDS * 4)
#define SMEM_BYTES (DEPTH * STAGE_BYTES)   // 65536 -> 2 blocks/SM

// k16 interleave: position pos holds k = (pos>>2) + 4*(pos&3); pos(k) = 4*(k&3) + ((k>>2)&3)
__host__ __device__ __forceinline__ int kperm(int j) {
    return (j & ~15) | (4 * (j & 3) + ((j >> 2) & 3));
}

// ---------------- scratch ----------------
__device__ float g_W0p[(K0/16) * G4 * 16];  // [k/16][p][16 pos], tf32, k-interleaved
__device__ float g_W1p[(K1/16) * G4 * 16];
__device__ float g_b0p[G4];
__device__ float g_b1p[G4];
__device__ float g_x32[B_ * T_ * I_];       // tf32-rounded, k-interleaved per 16
__device__ float g_h0 [2][B_ * H_];         // rounded, UNMASKED, j-interleaved
__device__ float g_h0m[2][B_ * H_];         // rounded, masked, j-interleaved
__device__ float g_h1m[2][B_ * H_];
__device__ float g_c0[B_ * H_];             // natural
__device__ float g_c1[B_ * H_];
__device__ float g_h0f[B_ * H_];            // exact h(T-1), natural
__device__ float g_h1f[B_ * H_];

// gate-column permutation: p -> original gate row q*H + j (groups of 16 cols = 4 units)
__device__ __forceinline__ int p2norig(int p) {
    int g = p >> 4, pp = p & 15;
    int q = (pp < 8) ? (pp & 1) : (2 + (pp & 1));
    int u = (pp < 8) ? (pp >> 1) : ((pp - 8) >> 1);
    return q * H_ + g * 4 + u;
}

__device__ __forceinline__ uint32_t tf32_bits(float x) {
    uint32_t u;
    asm("cvt.rna.tf32.f32 %0, %1;" : "=r"(u) : "f"(x));
    return u;
}

__device__ __forceinline__ void cp16(uint32_t dst, const void* src) {
    asm volatile("cp.async.cg.shared.global [%0], [%1], 16;" :: "r"(dst), "l"(src));
}

// ---------------- prologue ----------------
__global__ void permute_kernel(const float* __restrict__ input,
                               const float* __restrict__ Wih0, const float* __restrict__ Whh0,
                               const float* __restrict__ bih0, const float* __restrict__ bhh0,
                               const float* __restrict__ Wih1, const float* __restrict__ Whh1,
                               const float* __restrict__ bih1, const float* __restrict__ bhh1)
{
    int stride = gridDim.x * blockDim.x;
    int tid0 = blockIdx.x * blockDim.x + threadIdx.x;

    for (int idx = tid0; idx < B_ * T_ * I_; idx += stride) {
        int base = idx & ~15, pos = idx & 15;
        int ksrc = base + (pos >> 2) + 4 * (pos & 3);
        g_x32[idx] = __uint_as_float(tf32_bits(input[ksrc]));
    }
    for (int idx = tid0; idx < (K0/16) * G4 * 16; idx += stride) {
        int pos = idx & 15;
        int p  = (idx >> 4) & (G4 - 1);
        int kb = idx >> 15;
        int k = kb * 16 + (pos >> 2) + 4 * (pos & 3);
        int norig = p2norig(p);
        float v = (k < I_) ? Wih0[norig * I_ + k] : Whh0[norig * H_ + (k - I_)];
        g_W0p[idx] = __uint_as_float(tf32_bits(v));
    }
    for (int idx = tid0; idx < (K1/16) * G4 * 16; idx += stride) {
        int pos = idx & 15;
        int p  = (idx >> 4) & (G4 - 1);
        int kb = idx >> 15;
        int k = kb * 16 + (pos >> 2) + 4 * (pos & 3);
        int norig = p2norig(p);
        float v = (k < H_) ? Wih1[norig * H_ + k] : Whh1[norig * H_ + (k - H_)];
        g_W1p[idx] = __uint_as_float(tf32_bits(v));
    }
    for (int p = tid0; p < G4; p += stride) {
        int norig = p2norig(p);
        g_b0p[p] = bih0[norig] + bhh0[norig];
        g_b1p[p] = bih1[norig] + bhh1[norig];
    }
}

__global__ void init_state_kernel(const float* __restrict__ h, const float* __restrict__ c,
                                  const int* __restrict__ is_init)
{
    int stride = gridDim.x * blockDim.x;
    for (int idx = blockIdx.x * blockDim.x + threadIdx.x; idx < B_ * H_; idx += stride) {
        int b = idx / H_, j = idx - b * H_;
        float m0 = is_init[b * T_] ? 0.0f : 1.0f;
        int jp = kperm(j);
        g_h0m[0][b * H_ + jp] = __uint_as_float(tf32_bits(h[b * 2 * H_ + j])) * m0;
        g_h1m[0][b * H_ + jp] = __uint_as_float(tf32_bits(h[b * 2 * H_ + H_ + j])) * m0;
        g_c0[idx] = c[b * 2 * H_ + j];
        g_c1[idx] = c[b * 2 * H_ + H_ + j];
    }
}

// ---------------- fused tf32 mma GEMM + LSTM cell ----------------
template<int LAYER>
__device__ __forceinline__ void lstm_step_body(
    uint32_t* __restrict__ smem,
    const int* __restrict__ is_init,
    float* __restrict__ out,
    int t)
{
    constexpr int K = (LAYER == 0) ? K0 : K1;
    constexpr int NSTAGE = K / BKK;                 // 24 or 32 (both % 4 == 0)
    const float* Wp = (LAYER == 0) ? g_W0p : g_W1p;
    const float* bp = (LAYER == 0) ? g_b0p : g_b1p;
    const int ping = t & 1;
    const float* hmsk = (LAYER == 0) ? g_h0m[ping] : g_h1m[ping];
    const float* h0u  = g_h0[ping ^ 1];
    float* cbuf = (LAYER == 0) ? g_c0 : g_c1;

    const int tid = threadIdx.x;
    const int bn = blockIdx.x;               // 0..31 (64 gate cols)
    const int bm = blockIdx.y;               // 0..3  (64 batch rows)
    const int wid = tid >> 5, lane = tid & 31;
    const int wm = wid >> 2;                 // 0..1
    const int wn = wid & 3;                  // 0..3
    const int gi = lane >> 2;                // 0..7
    const int tg = lane & 3;                 // 0..3

    const uint32_t sbase = (uint32_t)__cvta_generic_to_shared(smem);

    // ---- hoisted producer state ----
    // A: 2 chunks/thread (512 chunks); chunk c: qc=c&3, row=(c>>2)&63, ks16=c>>8
    const float* pA0[2]; const float* pA1[2]; int thrA[2]; uint32_t dstA[2];
    #pragma unroll
    for (int hh = 0; hh < 2; hh++) {
        int c = tid + 256 * hh;
        int qc = c & 3, row = (c >> 2) & 63, ks16 = c >> 8;
        int gb = bm * BM + row;
        if (LAYER == 0) {
            pA0[hh] = g_x32 + (size_t)gb * T_ * I_ + (size_t)t * I_ + ks16 * 16 + qc * 4;
            pA1[hh] = hmsk + (size_t)gb * H_ + ks16 * 16 + qc * 4 - I_;
            thrA[hh] = I_ - ks16 * 16;
        } else {
            pA0[hh] = h0u + (size_t)gb * H_ + ks16 * 16 + qc * 4;
            pA1[hh] = hmsk + (size_t)gb * H_ + ks16 * 16 + qc * 4 - H_;
            thrA[hh] = H_ - ks16 * 16;
        }
        dstA[hh] = sbase + (ks16 * BM * 16 + row * 16 + qc * 4) * 4;
    }
    // B: 2 chunks/thread (512 chunks); pointer advances 2*G4*16 floats per stage
    const float* pB[2]; uint32_t dstB[2];
    #pragma unroll
    for (int hh = 0; hh < 2; hh++) {
        int c = tid + 256 * hh;
        int qc = c & 3, n = (c >> 2) & 63, ks16 = c >> 8;
        pB[hh] = Wp + ((size_t)ks16 * G4 + bn * BN + n) * 16 + qc * 4;
        dstB[hh] = sbase + (A_ST + ks16 * BN * 16 + n * 16 + qc * 4) * 4;
    }

    auto issue = [&](int k0, uint32_t bo) {
        #pragma unroll
        for (int hh = 0; hh < 2; hh++) {
            const float* s = (k0 < thrA[hh]) ? (pA0[hh] + k0) : (pA1[hh] + k0);
            cp16(dstA[hh] + bo, s);
        }
        #pragma unroll
        for (int hh = 0; hh < 2; hh++) {
            cp16(dstB[hh] + bo, pB[hh]);
            pB[hh] += 2 * G4 * 16;
        }
    };

    float acc[2][2][4] = {};

    issue(0, 0);
    asm volatile("cp.async.commit_group;" ::: "memory");
    issue(BKK, STAGE_BYTES);
    asm volatile("cp.async.commit_group;" ::: "memory");
    issue(2 * BKK, 2 * STAGE_BYTES);
    asm volatile("cp.async.commit_group;" ::: "memory");

    int kIss = 3 * BKK;
    for (int st4 = 0; st4 < NSTAGE; st4 += 4) {
        #pragma unroll
        for (int ii = 0; ii < 4; ii++) {
            const int st = st4 + ii;
            asm volatile("cp.async.wait_group 2;" ::: "memory");
            __syncthreads();

            if (st + 3 < NSTAGE)
                issue(kIss, (uint32_t)(((ii + 3) & 3) * STAGE_BYTES));
            kIss += BKK;
            asm volatile("cp.async.commit_group;" ::: "memory");

            const uint32_t* Ab = smem + ii * STAGE_WORDS;   // compile-time offset
            const uint32_t* Bb = Ab + A_ST;

            #pragma unroll
            for (int ks16 = 0; ks16 < 2; ks16++) {
                uint4 va[2][2], vb[2];
                #pragma unroll
                for (int mt = 0; mt < 2; mt++) {
                    int m0 = wm * 32 + mt * 16 + gi;
                    va[mt][0] = *(const uint4*)(Ab + ks16 * BM * 16 + m0 * 16 + tg * 4);
                    va[mt][1] = *(const uint4*)(Ab + ks16 * BM * 16 + (m0 + 8) * 16 + tg * 4);
                }
                #pragma unroll
                for (int nt = 0; nt < 2; nt++) {
                    int n0 = wn * 16 + nt * 8 + gi;
                    vb[nt] = *(const uint4*)(Bb + ks16 * BN * 16 + n0 * 16 + tg * 4);
                }
                #pragma unroll
                for (int mt = 0; mt < 2; mt++)
                    #pragma unroll
                    for (int nt = 0; nt < 2; nt++)
                        asm volatile(
                            "mma.sync.aligned.m16n8k8.row.col.f32.tf32.tf32.f32 "
                            "{%0,%1,%2,%3},{%4,%5,%6,%7},{%8,%9},{%0,%1,%2,%3};"
                            : "+f"(acc[mt][nt][0]), "+f"(acc[mt][nt][1]),
                              "+f"(acc[mt][nt][2]), "+f"(acc[mt][nt][3])
                            : "r"(va[mt][0].x), "r"(va[mt][1].x),
                              "r"(va[mt][0].y), "r"(va[mt][1].y),
                              "r"(vb[nt].x), "r"(vb[nt].y));
                #pragma unroll
                for (int mt = 0; mt < 2; mt++)
                    #pragma unroll
                    for (int nt = 0; nt < 2; nt++)
                        asm volatile(
                            "mma.sync.aligned.m16n8k8.row.col.f32.tf32.tf32.f32 "
                            "{%0,%1,%2,%3},{%4,%5,%6,%7},{%8,%9},{%0,%1,%2,%3};"
                            : "+f"(acc[mt][nt][0]), "+f"(acc[mt][nt][1]),
                              "+f"(acc[mt][nt][2]), "+f"(acc[mt][nt][3])
                            : "r"(va[mt][0].z), "r"(va[mt][1].z),
                              "r"(va[mt][0].w), "r"(va[mt][1].w),
                              "r"(vb[nt].z), "r"(vb[nt].w));
            }
        }
    }

    // ---- fused LSTM cell epilogue ----
    float* h0u_w = g_h0[ping ^ 1];
    float* hm_w  = (LAYER == 0) ? g_h0m[ping ^ 1] : g_h1m[ping ^ 1];
    float* hf_w  = (LAYER == 0) ? g_h0f : g_h1f;

    const int g = bn * 4 + wn;               // group of 4 hidden units (16 cols)
    const int j = g * 4 + tg;
    const int jp = kperm(j);
    const float bi = bp[g * 16 + 2 * tg];
    const float bf = bp[g * 16 + 2 * tg + 1];
    const float bg = bp[g * 16 + 8 + 2 * tg];
    const float bo = bp[g * 16 + 9 + 2 * tg];

    #pragma unroll
    for (int mt = 0; mt < 2; mt++)
        #pragma unroll
        for (int rr = 0; rr < 2; rr++) {
            int b = bm * BM + wm * 32 + mt * 16 + rr * 8 + gi;
            float ig = acc[mt][0][rr * 2 + 0] + bi;
            float fg = acc[mt][0][rr * 2 + 1] + bf;
            float gg = acc[mt][1][rr * 2 + 0] + bg;
            float og = acc[mt][1][rr * 2 + 1] + bo;
            float si = 1.0f / (1.0f + expf(-ig));
            float sf = 1.0f / (1.0f + expf(-fg));
            float so = 1.0f / (1.0f + expf(-og));
            float tgh = tanhf(gg);
            float cold = is_init[b * T_ + t] ? 0.0f : cbuf[b * H_ + j];
            float cn = sf * cold + si * tgh;
            float hn = so * tanhf(cn);
            cbuf[b * H_ + j] = cn;

            float hr = __uint_as_float(tf32_bits(hn));
            float mnext = 1.0f;
            if (t + 1 < T_) mnext = is_init[b * T_ + t + 1] ? 0.0f : 1.0f;
            hm_w[b * H_ + jp] = hr * mnext;
            if (LAYER == 0) h0u_w[b * H_ + jp] = hr;
            if (t == T_ - 1) hf_w[b * H_ + j] = hn;
            if (LAYER == 1)
                out[(size_t)b * T_ * H_ + (size_t)t * H_ + j] = hn;
        }
}

// Wavefront-fused launch s: z=0 -> layer0(time s), z=1 -> layer1(time s-1).
__global__ void __launch_bounds__(256, 2) fused_step_kernel(
    const int* __restrict__ is_init,
    float* __restrict__ out,
    int s)
{
    extern __shared__ uint32_t smem[];
    if (blockIdx.z == 0) {
        if (s < T_) lstm_step_body<0>(smem, is_init, out, s);
    } else {
        if (s >= 1) lstm_step_body<1>(smem, is_init, out, s - 1);
    }
}

// ---------------- finalize ----------------
__global__ void finalize_kernel(float* __restrict__ out)
{
    const size_t off1 = (size_t)B_ * T_ * H_;
    const size_t off2 = off1 + (size_t)B_ * 2 * H_;
    int stride = gridDim.x * blockDim.x;
    for (int idx = blockIdx.x * blockDim.x + threadIdx.x; idx < B_ * H_; idx += stride) {
        int b = idx / H_, j = idx - b * H_;
        out[off1 + (size_t)b * 2 * H_ + j]      = g_h0f[idx];
        out[off1 + (size_t)b * 2 * H_ + H_ + j] = g_h1f[idx];
        out[off2 + (size_t)b * 2 * H_ + j]      = g_c0[idx];
        out[off2 + (size_t)b * 2 * H_ + H_ + j] = g_c1[idx];
    }
}

extern "C" void kernel_launch(void* const* d_in, const int* in_sizes, int n_in,
                              void* d_out, int out_size)
{
    const float* input   = (const float*)d_in[0];
    const int*   is_init = (const int*)d_in[1];
    const float* h       = (const float*)d_in[2];
    const float* c       = (const float*)d_in[3];
    const float* Wih0    = (const float*)d_in[4];
    const float* Whh0    = (const float*)d_in[5];
    const float* bih0    = (const float*)d_in[6];
    const float* bhh0    = (const float*)d_in[7];
    const float* Wih1    = (const float*)d_in[8];
    const float* Whh1    = (const float*)d_in[9];
    const float* bih1    = (const float*)d_in[10];
    const float* bhh1    = (const float*)d_in[11];
    float* out = (float*)d_out;

    static bool attr_set = false;
    if (!attr_set) {
        cudaFuncSetAttribute(fused_step_kernel,
                             cudaFuncAttributeMaxDynamicSharedMemorySize, SMEM_BYTES);
        attr_set = true;
    }

    permute_kernel<<<296, 256>>>(input, Wih0, Whh0, bih0, bhh0, Wih1, Whh1, bih1, bhh1);
    init_state_kernel<<<148, 256>>>(h, c, is_init);

    dim3 grid(G4 / BN, B_ / BM, 2);   // (32, 4, 2) = 256 blocks, 2 blocks/SM
    for (int s = 0; s <= T_; s++)
        fused_step_kernel<<<grid, 256, SMEM_BYTES>>>(is_init, out, s);

    finalize_kernel<<<148, 256>>>(out);
}

// round 14
// speedup vs baseline: 1.0635x; 1.0451x over previous
#include <cuda_runtime.h>
#include <math.h>
#include <stdint.h>

// Problem dims
#define B_  256
#define T_  128
#define I_  256
#define H_  512
#define G4  2048   // 4*H
#define K0  768    // I + H
#define K1  1024   // H + H

// GEMM tile: block 64(m) x 64(n), 8 warps (2m x 4n), warp 32x16, stage BK=32
#define BM  64
#define BN  64
#define BKK 32
#define DEPTH 4

#define A_ST (2 * BM * 16)            // 2048 words
#define B_ST (2 * BN * 16)            // 2048 words
#define STAGE_WORDS (A_ST + B_ST)     // 4096 words = 16KB
#define SMEM_BYTES (DEPTH * STAGE_WORDS * 4)   // 65536 -> 2 blocks/SM

// k16 interleave: position pos holds k = (pos>>2) + 4*(pos&3); pos(k) = 4*(k&3) + ((k>>2)&3)
__host__ __device__ __forceinline__ int kperm(int j) {
    return (j & ~15) | (4 * (j & 3) + ((j >> 2) & 3));
}

// ---------------- scratch ----------------
__device__ float g_W0p[(K0/16) * G4 * 16];  // [k/16][p][16 pos], tf32, k-interleaved
__device__ float g_W1p[(K1/16) * G4 * 16];
__device__ float g_b0p[G4];
__device__ float g_b1p[G4];
__device__ float g_x32[B_ * T_ * I_];       // tf32-rounded, k-interleaved per 16
__device__ float g_h0 [2][B_ * H_];         // rounded, UNMASKED, j-interleaved
__device__ float g_h0m[2][B_ * H_];         // rounded, masked, j-interleaved
__device__ float g_h1m[2][B_ * H_];
__device__ float g_c0[B_ * H_];             // natural
__device__ float g_c1[B_ * H_];
__device__ float g_h0f[B_ * H_];            // exact h(T-1), natural
__device__ float g_h1f[B_ * H_];
__device__ unsigned g_bar[4 * 32];          // per-bm barrier counters, 128B apart

// gate-column permutation: p -> original gate row q*H + j (groups of 16 cols = 4 units)
__device__ __forceinline__ int p2norig(int p) {
    int g = p >> 4, pp = p & 15;
    int q = (pp < 8) ? (pp & 1) : (2 + (pp & 1));
    int u = (pp < 8) ? (pp >> 1) : ((pp - 8) >> 1);
    return q * H_ + g * 4 + u;
}

__device__ __forceinline__ uint32_t tf32_bits(float x) {
    uint32_t u;
    asm("cvt.rna.tf32.f32 %0, %1;" : "=r"(u) : "f"(x));
    return u;
}

__device__ __forceinline__ void cp16(uint32_t dst, const void* src) {
    asm volatile("cp.async.cg.shared.global [%0], [%1], 16;" :: "r"(dst), "l"(src));
}

// ---------------- prologue ----------------
__global__ void permute_kernel(const float* __restrict__ input,
                               const float* __restrict__ Wih0, const float* __restrict__ Whh0,
                               const float* __restrict__ bih0, const float* __restrict__ bhh0,
                               const float* __restrict__ Wih1, const float* __restrict__ Whh1,
                               const float* __restrict__ bih1, const float* __restrict__ bhh1)
{
    int stride = gridDim.x * blockDim.x;
    int tid0 = blockIdx.x * blockDim.x + threadIdx.x;

    for (int idx = tid0; idx < B_ * T_ * I_; idx += stride) {
        int base = idx & ~15, pos = idx & 15;
        int ksrc = base + (pos >> 2) + 4 * (pos & 3);
        g_x32[idx] = __uint_as_float(tf32_bits(input[ksrc]));
    }
    for (int idx = tid0; idx < (K0/16) * G4 * 16; idx += stride) {
        int pos = idx & 15;
        int p  = (idx >> 4) & (G4 - 1);
        int kb = idx >> 15;
        int k = kb * 16 + (pos >> 2) + 4 * (pos & 3);
        int norig = p2norig(p);
        float v = (k < I_) ? Wih0[norig * I_ + k] : Whh0[norig * H_ + (k - I_)];
        g_W0p[idx] = __uint_as_float(tf32_bits(v));
    }
    for (int idx = tid0; idx < (K1/16) * G4 * 16; idx += stride) {
        int pos = idx & 15;
        int p  = (idx >> 4) & (G4 - 1);
        int kb = idx >> 15;
        int k = kb * 16 + (pos >> 2) + 4 * (pos & 3);
        int norig = p2norig(p);
        float v = (k < H_) ? Wih1[norig * H_ + k] : Whh1[norig * H_ + (k - H_)];
        g_W1p[idx] = __uint_as_float(tf32_bits(v));
    }
    for (int p = tid0; p < G4; p += stride) {
        int norig = p2norig(p);
        g_b0p[p] = bih0[norig] + bhh0[norig];
        g_b1p[p] = bih1[norig] + bhh1[norig];
    }
}

__global__ void init_state_kernel(const float* __restrict__ h, const float* __restrict__ c,
                                  const int* __restrict__ is_init)
{
    if (blockIdx.x == 0 && threadIdx.x < 4)
        g_bar[threadIdx.x * 32] = 0;          // reset barrier counters each replay
    int stride = gridDim.x * blockDim.x;
    for (int idx = blockIdx.x * blockDim.x + threadIdx.x; idx < B_ * H_; idx += stride) {
        int b = idx / H_, j = idx - b * H_;
        float m0 = is_init[b * T_] ? 0.0f : 1.0f;
        int jp = kperm(j);
        g_h0m[0][b * H_ + jp] = __uint_as_float(tf32_bits(h[b * 2 * H_ + j])) * m0;
        g_h1m[0][b * H_ + jp] = __uint_as_float(tf32_bits(h[b * 2 * H_ + H_ + j])) * m0;
        g_c0[idx] = c[b * 2 * H_ + j];
        g_c1[idx] = c[b * 2 * H_ + H_ + j];
    }
}

// ---------------- fused tf32 mma GEMM + LSTM cell (R11 body, parameterized) ----------------
template<int LAYER>
__device__ __forceinline__ void lstm_step_body(
    uint32_t* __restrict__ smem,
    const int* __restrict__ is_init,
    float* __restrict__ out,
    int t, int bn, int bm)
{
    constexpr int K = (LAYER == 0) ? K0 : K1;
    constexpr int NSTAGE = K / BKK;                 // 24 or 32
    const float* Wp = (LAYER == 0) ? g_W0p : g_W1p;
    const float* bp = (LAYER == 0) ? g_b0p : g_b1p;
    const int ping = t & 1;
    const float* hmsk = (LAYER == 0) ? g_h0m[ping] : g_h1m[ping];
    const float* h0u  = g_h0[ping ^ 1];
    float* cbuf = (LAYER == 0) ? g_c0 : g_c1;

    const int tid = threadIdx.x;
    const int wid = tid >> 5, lane = tid & 31;
    const int wm = wid >> 2;                 // 0..1
    const int wn = wid & 3;                  // 0..3
    const int gi = lane >> 2;                // 0..7
    const int tg = lane & 3;                 // 0..3

    const uint32_t sbase = (uint32_t)__cvta_generic_to_shared(smem);

    // producer: A 512 chunks (2/thread), B 512 chunks (2/thread); chunk = 16B
    auto issue = [&](int st, int buf) {
        const int k0 = st * BKK;
        const uint32_t stB = sbase + buf * STAGE_WORDS * 4;
        #pragma unroll
        for (int hh = 0; hh < 2; hh++) {
            int c = tid + 256 * hh;
            int qc = c & 3, row = (c >> 2) & 63, ks16 = c >> 8;
            int base16 = k0 + ks16 * 16;
            int gb = bm * BM + row;
            const float* src;
            if (LAYER == 0)
                src = (base16 < I_)
                    ? (g_x32 + (size_t)gb * T_ * I_ + (size_t)t * I_ + base16 + qc * 4)
                    : (hmsk + (size_t)gb * H_ + (base16 - I_) + qc * 4);
            else
                src = (base16 < H_)
                    ? (h0u + (size_t)gb * H_ + base16 + qc * 4)
                    : (hmsk + (size_t)gb * H_ + (base16 - H_) + qc * 4);
            cp16(stB + (ks16 * BM * 16 + row * 16 + qc * 4) * 4, src);
        }
        #pragma unroll
        for (int hh = 0; hh < 2; hh++) {
            int c = tid + 256 * hh;
            int qc = c & 3, n = (c >> 2) & 63, ks16 = c >> 8;
            int kb = (k0 >> 4) + ks16;
            const float* src = Wp + ((size_t)kb * G4 + bn * BN + n) * 16 + qc * 4;
            cp16(stB + (A_ST + ks16 * BN * 16 + n * 16 + qc * 4) * 4, src);
        }
    };

    float acc[2][2][4] = {};

    issue(0, 0); asm volatile("cp.async.commit_group;" ::: "memory");
    issue(1, 1); asm volatile("cp.async.commit_group;" ::: "memory");
    issue(2, 2); asm volatile("cp.async.commit_group;" ::: "memory");

    int buf = 0, nbuf = 3;
    for (int st = 0; st < NSTAGE; st++) {
        asm volatile("cp.async.wait_group 2;" ::: "memory");
        __syncthreads();

        if (st + 3 < NSTAGE) issue(st + 3, nbuf);
        asm volatile("cp.async.commit_group;" ::: "memory");

        const uint32_t* Ab = smem + buf * STAGE_WORDS;
        const uint32_t* Bb = Ab + A_ST;

        #pragma unroll
        for (int ks16 = 0; ks16 < 2; ks16++) {
            uint4 va[2][2], vb[2];
            #pragma unroll
            for (int mt = 0; mt < 2; mt++) {
                int m0 = wm * 32 + mt * 16 + gi;
                va[mt][0] = *(const uint4*)(Ab + ks16 * BM * 16 + m0 * 16 + tg * 4);
                va[mt][1] = *(const uint4*)(Ab + ks16 * BM * 16 + (m0 + 8) * 16 + tg * 4);
            }
            #pragma unroll
            for (int nt = 0; nt < 2; nt++) {
                int n0 = wn * 16 + nt * 8 + gi;
                vb[nt] = *(const uint4*)(Bb + ks16 * BN * 16 + n0 * 16 + tg * 4);
            }
            #pragma unroll
            for (int mt = 0; mt < 2; mt++)
                #pragma unroll
                for (int nt = 0; nt < 2; nt++)
                    asm volatile(
                        "mma.sync.aligned.m16n8k8.row.col.f32.tf32.tf32.f32 "
                        "{%0,%1,%2,%3},{%4,%5,%6,%7},{%8,%9},{%0,%1,%2,%3};"
                        : "+f"(acc[mt][nt][0]), "+f"(acc[mt][nt][1]),
                          "+f"(acc[mt][nt][2]), "+f"(acc[mt][nt][3])
                        : "r"(va[mt][0].x), "r"(va[mt][1].x),
                          "r"(va[mt][0].y), "r"(va[mt][1].y),
                          "r"(vb[nt].x), "r"(vb[nt].y));
            #pragma unroll
            for (int mt = 0; mt < 2; mt++)
                #pragma unroll
                for (int nt = 0; nt < 2; nt++)
                    asm volatile(
                        "mma.sync.aligned.m16n8k8.row.col.f32.tf32.tf32.f32 "
                        "{%0,%1,%2,%3},{%4,%5,%6,%7},{%8,%9},{%0,%1,%2,%3};"
                        : "+f"(acc[mt][nt][0]), "+f"(acc[mt][nt][1]),
                          "+f"(acc[mt][nt][2]), "+f"(acc[mt][nt][3])
                        : "r"(va[mt][0].z), "r"(va[mt][1].z),
                          "r"(va[mt][0].w), "r"(va[mt][1].w),
                          "r"(vb[nt].z), "r"(vb[nt].w));
        }

        buf = (buf + 1) & (DEPTH - 1);
        nbuf = (nbuf + 1) & (DEPTH - 1);
    }

    // ---- fused LSTM cell epilogue ----
    float* h0u_w = g_h0[ping ^ 1];
    float* hm_w  = (LAYER == 0) ? g_h0m[ping ^ 1] : g_h1m[ping ^ 1];
    float* hf_w  = (LAYER == 0) ? g_h0f : g_h1f;

    const int g = bn * 4 + wn;
    const int j = g * 4 + tg;
    const int jp = kperm(j);
    const float bi = bp[g * 16 + 2 * tg];
    const float bf = bp[g * 16 + 2 * tg + 1];
    const float bg = bp[g * 16 + 8 + 2 * tg];
    const float bo = bp[g * 16 + 9 + 2 * tg];

    #pragma unroll
    for (int mt = 0; mt < 2; mt++)
        #pragma unroll
        for (int rr = 0; rr < 2; rr++) {
            int b = bm * BM + wm * 32 + mt * 16 + rr * 8 + gi;
            float ig = acc[mt][0][rr * 2 + 0] + bi;
            float fg = acc[mt][0][rr * 2 + 1] + bf;
            float gg = acc[mt][1][rr * 2 + 0] + bg;
            float og = acc[mt][1][rr * 2 + 1] + bo;
            float si = 1.0f / (1.0f + expf(-ig));
            float sf = 1.0f / (1.0f + expf(-fg));
            float so = 1.0f / (1.0f + expf(-og));
            float tgh = tanhf(gg);
            float cold = is_init[b * T_ + t] ? 0.0f : cbuf[b * H_ + j];
            float cn = sf * cold + si * tgh;
            float hn = so * tanhf(cn);
            cbuf[b * H_ + j] = cn;

            float hr = __uint_as_float(tf32_bits(hn));
            float mnext = 1.0f;
            if (t + 1 < T_) mnext = is_init[b * T_ + t + 1] ? 0.0f : 1.0f;
            hm_w[b * H_ + jp] = hr * mnext;
            if (LAYER == 0) h0u_w[b * H_ + jp] = hr;
            if (t == T_ - 1) hf_w[b * H_ + j] = hn;
            if (LAYER == 1)
                out[(size_t)b * T_ * H_ + (size_t)t * H_ + j] = hn;
        }
}

// per-bm group barrier: 64 blocks (32 layer0 + 32 layer1 sharing the same bm)
__device__ __forceinline__ void group_barrier(int bm, unsigned target)
{
    __threadfence();
    __syncthreads();
    if (threadIdx.x == 0) {
        atomicAdd(&g_bar[bm * 32], 1u);
        while (*(volatile unsigned*)&g_bar[bm * 32] < target)
            __nanosleep(64);
        __threadfence();
    }
    __syncthreads();
}

// ---------------- persistent kernel: all 129 wavefront phases in ONE launch ----------------
__global__ void __launch_bounds__(256, 2) lstm_persistent_kernel(
    const int* __restrict__ is_init,
    float* __restrict__ out)
{
    extern __shared__ uint32_t smem[];
    const int layer = blockIdx.x >> 7;       // 0..1
    const int bidl  = blockIdx.x & 127;
    const int bn = bidl & 31;                // 0..31
    const int bm = bidl >> 5;                // 0..3

    for (int s = 0; s <= T_; s++) {
        if (layer == 0) {
            if (s < T_) lstm_step_body<0>(smem, is_init, out, s, bn, bm);
        } else {
            if (s >= 1) lstm_step_body<1>(smem, is_init, out, s - 1, bn, bm);
        }
        if (s < T_)
            group_barrier(bm, 64u * (unsigned)(s + 1));
    }
}

// ---------------- finalize ----------------
__global__ void finalize_kernel(float* __restrict__ out)
{
    const size_t off1 = (size_t)B_ * T_ * H_;
    const size_t off2 = off1 + (size_t)B_ * 2 * H_;
    int stride = gridDim.x * blockDim.x;
    for (int idx = blockIdx.x * blockDim.x + threadIdx.x; idx < B_ * H_; idx += stride) {
        int b = idx / H_, j = idx - b * H_;
        out[off1 + (size_t)b * 2 * H_ + j]      = g_h0f[idx];
        out[off1 + (size_t)b * 2 * H_ + H_ + j] = g_h1f[idx];
        out[off2 + (size_t)b * 2 * H_ + j]      = g_c0[idx];
        out[off2 + (size_t)b * 2 * H_ + H_ + j] = g_c1[idx];
    }
}

extern "C" void kernel_launch(void* const* d_in, const int* in_sizes, int n_in,
                              void* d_out, int out_size)
{
    const float* input   = (const float*)d_in[0];
    const int*   is_init = (const int*)d_in[1];
    const float* h       = (const float*)d_in[2];
    const float* c       = (const float*)d_in[3];
    const float* Wih0    = (const float*)d_in[4];
    const float* Whh0    = (const float*)d_in[5];
    const float* bih0    = (const float*)d_in[6];
    const float* bhh0    = (const float*)d_in[7];
    const float* Wih1    = (const float*)d_in[8];
    const float* Whh1    = (const float*)d_in[9];
    const float* bih1    = (const float*)d_in[10];
    const float* bhh1    = (const float*)d_in[11];
    float* out = (float*)d_out;

    static bool attr_set = false;
    if (!attr_set) {
        cudaFuncSetAttribute(lstm_persistent_kernel,
                             cudaFuncAttributeMaxDynamicSharedMemorySize, SMEM_BYTES);
        attr_set = true;
    }

    permute_kernel<<<296, 256>>>(input, Wih0, Whh0, bih0, bhh0, Wih1, Whh1, bih1, bhh1);
    init_state_kernel<<<148, 256>>>(h, c, is_init);

    lstm_persistent_kernel<<<256, 256, SMEM_BYTES>>>(is_init, out);

    finalize_kernel<<<148, 256>>>(out);
}

// round 15
// speedup vs baseline: 1.8073x; 1.6995x over previous
#include <cuda_runtime.h>
#include <cuda_fp16.h>
#include <math.h>
#include <stdint.h>

// Problem dims
#define B_  256
#define T_  128
#define I_  256
#define H_  512
#define G4  2048   // 4*H
#define K0  768    // I + H
#define K1  1024   // H + H

// GEMM tile: block 64(m) x 64(n), 8 warps (2m x 4n), warp 32x16, stage BK=64 (fp16)
#define BM  64
#define BN  64
#define BKK 64
#define DEPTH 4

// smem per stage: A [2 g32][64 rows][64B] + B same = 16KB
#define A_ST (2 * BM * 16)            // 2048 words (8KB)
#define B_ST (2 * BN * 16)            // 2048 words
#define STAGE_WORDS (A_ST + B_ST)     // 4096 words = 16KB
#define SMEM_BYTES (DEPTH * STAGE_WORDS * 4)   // 65536 -> 2 blocks/SM

// fp16 k32 interleave: chunk tg (16B, 8 fp16) holds k = {2tg,2tg+1,2tg+8,2tg+9,2tg+16,2tg+17,2tg+24,2tg+25}
// pos(k) = (k&~31) + ((k&7)>>1)*8 + ((k>>3)&3)*2 + (k&1)
__host__ __device__ __forceinline__ int hperm(int k) {
    return (k & ~31) + (((k & 7) >> 1) << 3) + (((k >> 3) & 3) << 1) + (k & 1);
}
// inverse: pos -> k
__host__ __device__ __forceinline__ int hperm_inv(int pos) {
    int tg = (pos >> 3) & 3, slot = pos & 7;
    return (pos & ~31) + 2 * tg + (slot & 1) + 8 * (slot >> 1);
}

// ---------------- scratch ----------------
__device__ __half g_W0h[(K0/32) * G4 * 32];  // [k/32][p][32 pos], fp16, k-interleaved
__device__ __half g_W1h[(K1/32) * G4 * 32];
__device__ float  g_b0p[G4];
__device__ float  g_b1p[G4];
__device__ __half g_x16[B_ * T_ * I_];       // fp16, k-interleaved per 32
__device__ __half g_h0 [2][B_ * H_];         // fp16, UNMASKED, j-interleaved
__device__ __half g_h0m[2][B_ * H_];         // fp16, masked, j-interleaved
__device__ __half g_h1m[2][B_ * H_];
__device__ float  g_c0[B_ * H_];             // natural fp32
__device__ float  g_c1[B_ * H_];
__device__ float  g_h0f[B_ * H_];            // exact h(T-1), natural
__device__ float  g_h1f[B_ * H_];

// gate-column permutation: p -> original gate row q*H + j (groups of 16 cols = 4 units)
__device__ __forceinline__ int p2norig(int p) {
    int g = p >> 4, pp = p & 15;
    int q = (pp < 8) ? (pp & 1) : (2 + (pp & 1));
    int u = (pp < 8) ? (pp >> 1) : ((pp - 8) >> 1);
    return q * H_ + g * 4 + u;
}

__device__ __forceinline__ void cp16(uint32_t dst, const void* src) {
    asm volatile("cp.async.cg.shared.global [%0], [%1], 16;" :: "r"(dst), "l"(src));
}

// ---------------- prologue ----------------
__global__ void permute_kernel(const float* __restrict__ input,
                               const float* __restrict__ Wih0, const float* __restrict__ Whh0,
                               const float* __restrict__ bih0, const float* __restrict__ bhh0,
                               const float* __restrict__ Wih1, const float* __restrict__ Whh1,
                               const float* __restrict__ bih1, const float* __restrict__ bhh1)
{
    int stride = gridDim.x * blockDim.x;
    int tid0 = blockIdx.x * blockDim.x + threadIdx.x;

    for (int idx = tid0; idx < B_ * T_ * I_; idx += stride) {
        int base = idx & ~31, pos = idx & 31;
        int ksrc = base + (hperm_inv(pos) & 31);
        g_x16[idx] = __float2half(input[ksrc]);
    }
    // W: [kb][p][32 pos];  kb index = idx >> 16 (32*2048 = 65536)
    for (int idx = tid0; idx < (K0/32) * G4 * 32; idx += stride) {
        int pos = idx & 31;
        int p  = (idx >> 5) & (G4 - 1);
        int kb = idx >> 16;
        int k = kb * 32 + (hperm_inv(pos) & 31);
        int norig = p2norig(p);
        float v = (k < I_) ? Wih0[norig * I_ + k] : Whh0[norig * H_ + (k - I_)];
        g_W0h[idx] = __float2half(v);
    }
    for (int idx = tid0; idx < (K1/32) * G4 * 32; idx += stride) {
        int pos = idx & 31;
        int p  = (idx >> 5) & (G4 - 1);
        int kb = idx >> 16;
        int k = kb * 32 + (hperm_inv(pos) & 31);
        int norig = p2norig(p);
        float v = (k < H_) ? Wih1[norig * H_ + k] : Whh1[norig * H_ + (k - H_)];
        g_W1h[idx] = __float2half(v);
    }
    for (int p = tid0; p < G4; p += stride) {
        int norig = p2norig(p);
        g_b0p[p] = bih0[norig] + bhh0[norig];
        g_b1p[p] = bih1[norig] + bhh1[norig];
    }
}

__global__ void init_state_kernel(const float* __restrict__ h, const float* __restrict__ c,
                                  const int* __restrict__ is_init)
{
    int stride = gridDim.x * blockDim.x;
    for (int idx = blockIdx.x * blockDim.x + threadIdx.x; idx < B_ * H_; idx += stride) {
        int b = idx / H_, j = idx - b * H_;
        bool init0 = is_init[b * T_] != 0;
        int jp = hperm(j);
        float h0v = init0 ? 0.0f : h[b * 2 * H_ + j];
        float h1v = init0 ? 0.0f : h[b * 2 * H_ + H_ + j];
        g_h0m[0][b * H_ + jp] = __float2half(h0v);
        g_h1m[0][b * H_ + jp] = __float2half(h1v);
        g_c0[idx] = c[b * 2 * H_ + j];
        g_c1[idx] = c[b * 2 * H_ + H_ + j];
    }
}

// ---------------- fused fp16 mma GEMM + LSTM cell ----------------
template<int LAYER>
__device__ __forceinline__ void lstm_step_body(
    uint32_t* __restrict__ smem,
    const int* __restrict__ is_init,
    float* __restrict__ out,
    int t)
{
    constexpr int K = (LAYER == 0) ? K0 : K1;
    constexpr int NSTAGE = K / BKK;                 // 12 or 16
    constexpr int BOUND  = (LAYER == 0) ? I_ : H_;  // x/h boundary (stage-aligned)
    const __half* Wp = (LAYER == 0) ? g_W0h : g_W1h;
    const float* bp = (LAYER == 0) ? g_b0p : g_b1p;
    const int ping = t & 1;
    const __half* hmsk = (LAYER == 0) ? g_h0m[ping] : g_h1m[ping];
    const __half* h0u  = g_h0[ping ^ 1];
    float* cbuf = (LAYER == 0) ? g_c0 : g_c1;

    const int tid = threadIdx.x;
    const int bn = blockIdx.x;               // 0..31 (64 gate cols)
    const int bm = blockIdx.y;               // 0..3  (64 batch rows)
    const int wid = tid >> 5, lane = tid & 31;
    const int wm = wid >> 2;                 // 0..1
    const int wn = wid & 3;                  // 0..3
    const int gi = lane >> 2;                // 0..7
    const int tg = lane & 3;                 // 0..3

    const uint32_t sbase = (uint32_t)__cvta_generic_to_shared(smem);

    // producer: A 512 chunks (2/thread), B 512 chunks (2/thread); chunk = 16B = 8 fp16
    auto issue = [&](int st, int buf) {
        const int k0 = st * BKK;
        const uint32_t stB = sbase + buf * STAGE_WORDS * 4;
        #pragma unroll
        for (int hh = 0; hh < 2; hh++) {
            int c = tid + 256 * hh;
            int qc = c & 3, row = (c >> 2) & 63, g32 = c >> 8;
            int base16 = k0 + g32 * 32;
            int gb = bm * BM + row;
            const __half* src;
            if (LAYER == 0)
                src = (base16 < I_)
                    ? (g_x16 + ((size_t)gb * T_ + t) * I_ + base16 + qc * 8)
                    : (hmsk + (size_t)gb * H_ + (base16 - I_) + qc * 8);
            else
                src = (base16 < H_)
                    ? (h0u + (size_t)gb * H_ + base16 + qc * 8)
                    : (hmsk + (size_t)gb * H_ + (base16 - H_) + qc * 8);
            cp16(stB + (g32 * BM * 16 + row * 16 + qc * 4) * 4, src);
        }
        #pragma unroll
        for (int hh = 0; hh < 2; hh++) {
            int c = tid + 256 * hh;
            int qc = c & 3, n = (c >> 2) & 63, g32 = c >> 8;
            int kb = st * 2 + g32;
            const __half* src = Wp + ((size_t)kb * G4 + bn * BN + n) * 32 + qc * 8;
            cp16(stB + (A_ST + g32 * BN * 16 + n * 16 + qc * 4) * 4, src);
        }
    };

    float acc[2][2][4] = {};

    issue(0, 0); asm volatile("cp.async.commit_group;" ::: "memory");
    issue(1, 1); asm volatile("cp.async.commit_group;" ::: "memory");
    issue(2, 2); asm volatile("cp.async.commit_group;" ::: "memory");

    int buf = 0, nbuf = 3;
    for (int st = 0; st < NSTAGE; st++) {
        asm volatile("cp.async.wait_group 2;" ::: "memory");
        __syncthreads();

        if (st + 3 < NSTAGE) issue(st + 3, nbuf);
        asm volatile("cp.async.commit_group;" ::: "memory");

        const uint32_t* Ab = smem + buf * STAGE_WORDS;
        const uint32_t* Bb = Ab + A_ST;

        #pragma unroll
        for (int g32 = 0; g32 < 2; g32++) {
            uint4 va[2][2], vb[2];
            #pragma unroll
            for (int mt = 0; mt < 2; mt++) {
                int m0 = wm * 32 + mt * 16 + gi;
                va[mt][0] = *(const uint4*)(Ab + g32 * BM * 16 + m0 * 16 + tg * 4);
                va[mt][1] = *(const uint4*)(Ab + g32 * BM * 16 + (m0 + 8) * 16 + tg * 4);
            }
            #pragma unroll
            for (int nt = 0; nt < 2; nt++) {
                int n0 = wn * 16 + nt * 8 + gi;
                vb[nt] = *(const uint4*)(Bb + g32 * BN * 16 + n0 * 16 + tg * 4);
            }
            // slab 0: k[0..16) of this k32 group (.x = k{2tg,2tg+1}, .y = k{2tg+8,2tg+9})
            #pragma unroll
            for (int mt = 0; mt < 2; mt++)
                #pragma unroll
                for (int nt = 0; nt < 2; nt++)
                    asm volatile(
                        "mma.sync.aligned.m16n8k16.row.col.f32.f16.f16.f32 "
                        "{%0,%1,%2,%3},{%4,%5,%6,%7},{%8,%9},{%0,%1,%2,%3};"
                        : "+f"(acc[mt][nt][0]), "+f"(acc[mt][nt][1]),
                          "+f"(acc[mt][nt][2]), "+f"(acc[mt][nt][3])
                        : "r"(va[mt][0].x), "r"(va[mt][1].x),
                          "r"(va[mt][0].y), "r"(va[mt][1].y),
                          "r"(vb[nt].x), "r"(vb[nt].y));
            // slab 1: k[16..32) (.z, .w)
            #pragma unroll
            for (int mt = 0; mt < 2; mt++)
                #pragma unroll
                for (int nt = 0; nt < 2; nt++)
                    asm volatile(
                        "mma.sync.aligned.m16n8k16.row.col.f32.f16.f16.f32 "
                        "{%0,%1,%2,%3},{%4,%5,%6,%7},{%8,%9},{%0,%1,%2,%3};"
                        : "+f"(acc[mt][nt][0]), "+f"(acc[mt][nt][1]),
                          "+f"(acc[mt][nt][2]), "+f"(acc[mt][nt][3])
                        : "r"(va[mt][0].z), "r"(va[mt][1].z),
                          "r"(va[mt][0].w), "r"(va[mt][1].w),
                          "r"(vb[nt].z), "r"(vb[nt].w));
        }

        buf = (buf + 1) & (DEPTH - 1);
        nbuf = (nbuf + 1) & (DEPTH - 1);
    }

    // ---- fused LSTM cell epilogue ----
    __half* h0u_w = g_h0[ping ^ 1];
    __half* hm_w  = (LAYER == 0) ? g_h0m[ping ^ 1] : g_h1m[ping ^ 1];
    float*  hf_w  = (LAYER == 0) ? g_h0f : g_h1f;

    const int g = bn * 4 + wn;               // group of 4 hidden units (16 cols)
    const int j = g * 4 + tg;
    const int jp = hperm(j);
    const float bi = bp[g * 16 + 2 * tg];
    const float bf = bp[g * 16 + 2 * tg + 1];
    const float bg = bp[g * 16 + 8 + 2 * tg];
    const float bo = bp[g * 16 + 9 + 2 * tg];

    #pragma unroll
    for (int mt = 0; mt < 2; mt++)
        #pragma unroll
        for (int rr = 0; rr < 2; rr++) {
            int b = bm * BM + wm * 32 + mt * 16 + rr * 8 + gi;
            float ig = acc[mt][0][rr * 2 + 0] + bi;
            float fg = acc[mt][0][rr * 2 + 1] + bf;
            float gg = acc[mt][1][rr * 2 + 0] + bg;
            float og = acc[mt][1][rr * 2 + 1] + bo;
            float si = 1.0f / (1.0f + expf(-ig));
            float sf = 1.0f / (1.0f + expf(-fg));
            float so = 1.0f / (1.0f + expf(-og));
            float tgh = tanhf(gg);
            float cold = is_init[b * T_ + t] ? 0.0f : cbuf[b * H_ + j];
            float cn = sf * cold + si * tgh;
            float hn = so * tanhf(cn);
            cbuf[b * H_ + j] = cn;

            float mnext = 1.0f;
            if (t + 1 < T_) mnext = is_init[b * T_ + t + 1] ? 0.0f : 1.0f;
            hm_w[b * H_ + jp] = __float2half(hn * mnext);
            if (LAYER == 0) h0u_w[b * H_ + jp] = __float2half(hn);
            if (t == T_ - 1) hf_w[b * H_ + j] = hn;
            if (LAYER == 1)
                out[(size_t)b * T_ * H_ + (size_t)t * H_ + j] = hn;
        }
}

// Wavefront-fused launch s: z=0 -> layer0(time s), z=1 -> layer1(time s-1).
__global__ void __launch_bounds__(256, 2) fused_step_kernel(
    const int* __restrict__ is_init,
    float* __restrict__ out,
    int s)
{
    extern __shared__ uint32_t smem[];
    if (blockIdx.z == 0) {
        if (s < T_) lstm_step_body<0>(smem, is_init, out, s);
    } else {
        if (s >= 1) lstm_step_body<1>(smem, is_init, out, s - 1);
    }
}

// ---------------- finalize ----------------
__global__ void finalize_kernel(float* __restrict__ out)
{
    const size_t off1 = (size_t)B_ * T_ * H_;
    const size_t off2 = off1 + (size_t)B_ * 2 * H_;
    int stride = gridDim.x * blockDim.x;
    for (int idx = blockIdx.x * blockDim.x + threadIdx.x; idx < B_ * H_; idx += stride) {
        int b = idx / H_, j = idx - b * H_;
        out[off1 + (size_t)b * 2 * H_ + j]      = g_h0f[idx];
        out[off1 + (size_t)b * 2 * H_ + H_ + j] = g_h1f[idx];
        out[off2 + (size_t)b * 2 * H_ + j]      = g_c0[idx];
        out[off2 + (size_t)b * 2 * H_ + H_ + j] = g_c1[idx];
    }
}

extern "C" void kernel_launch(void* const* d_in, const int* in_sizes, int n_in,
                              void* d_out, int out_size)
{
    const float* input   = (const float*)d_in[0];
    const int*   is_init = (const int*)d_in[1];
    const float* h       = (const float*)d_in[2];
    const float* c       = (const float*)d_in[3];
    const float* Wih0    = (const float*)d_in[4];
    const float* Whh0    = (const float*)d_in[5];
    const float* bih0    = (const float*)d_in[6];
    const float* bhh0    = (const float*)d_in[7];
    const float* Wih1    = (const float*)d_in[8];
    const float* Whh1    = (const float*)d_in[9];
    const float* bih1    = (const float*)d_in[10];
    const float* bhh1    = (const float*)d_in[11];
    float* out = (float*)d_out;

    static bool attr_set = false;
    if (!attr_set) {
        cudaFuncSetAttribute(fused_step_kernel,
                             cudaFuncAttributeMaxDynamicSharedMemorySize, SMEM_BYTES);
        attr_set = true;
    }

    permute_kernel<<<296, 256>>>(input, Wih0, Whh0, bih0, bhh0, Wih1, Whh1, bih1, bhh1);
    init_state_kernel<<<148, 256>>>(h, c, is_init);

    dim3 grid(G4 / BN, B_ / BM, 2);   // (32, 4, 2) = 256 blocks, 2 blocks/SM
    for (int s = 0; s <= T_; s++)
        fused_step_kernel<<<grid, 256, SMEM_BYTES>>>(is_init, out, s);

    finalize_kernel<<<148, 256>>>(out);
}